// round 2
// baseline (speedup 1.0000x reference)
#include <cuda_runtime.h>
#include <cstdint>

// ---------------- problem constants ----------------
#define B 64
// conv1: 3 -> 128, 128x128 -> 64x64, k3 s2 p1
// conv2: 128 -> 256, 64x64 -> 32x32, k3 s2 p1
// pre:   256 -> 64 (1x1)
// VQ:    512 codes x 64 dims
// post:  64 -> 256 (1x1)
// dec1:  convT 256 -> 128, 32x32 -> 64x64, k3 s2 p1 op1
// dec2:  convT 128 -> 3,  64x64 -> 128x128, k3 s2 p1 op1

#define H1_ELEMS (64*128*64*64)   // 33554432
#define H2_ELEMS (64*256*32*32)   // 16777216
#define Z_ELEMS  (64*64*32*32)    // 4194304
#define D_ELEMS  (64*256*32*32)
#define D1_ELEMS (64*128*64*64)

#define RECON_ELEMS (64*3*128*128)  // 3145728
#define NVEC 65536                  // 64*32*32
#define VQ_DIM 64
#define NCODE 512

__device__ float g_h1[H1_ELEMS];
__device__ float g_h2[H2_ELEMS];
__device__ float g_z[Z_ELEMS];
__device__ float g_q[Z_ELEMS];
__device__ float g_d[D_ELEMS];
__device__ float g_d1[D1_ELEMS];
__device__ float g_psum[128*64];
__device__ float g_psq[128*64];
__device__ float g_scale[128];
__device__ float g_shift[128];
__device__ float g_losspart[256];

// ---------------- conv1: 3->128, s2, 128->64 ----------------
// grid (4,4,64) tiles of 16x16 outputs; block 256 = one thread per output px,
// each thread computes all 128 output channels (weights broadcast from smem).
__global__ void conv1_kernel(const float* __restrict__ x,
                             const float* __restrict__ w,
                             const float* __restrict__ bias,
                             float* __restrict__ out)
{
    __shared__ float w_s[128*27];
    __shared__ float in_s[3*33*33];
    int n = blockIdx.z;
    int OH0 = blockIdx.y * 16, OW0 = blockIdx.x * 16;
    int tid = threadIdx.x;

    for (int i = tid; i < 128*27; i += 256) w_s[i] = w[i];
    int IH0 = OH0*2 - 1, IW0 = OW0*2 - 1;
    for (int i = tid; i < 3*33*33; i += 256) {
        int ci = i / 1089; int r = (i % 1089) / 33; int c = i % 33;
        int ih = IH0 + r, iw = IW0 + c;
        float v = 0.f;
        if (ih >= 0 && ih < 128 && iw >= 0 && iw < 128)
            v = x[((n*3 + ci)*128 + ih)*128 + iw];
        in_s[i] = v;
    }
    __syncthreads();

    int ty = tid >> 4, tx = tid & 15;
    float in_r[27];
#pragma unroll
    for (int ci = 0; ci < 3; ci++)
#pragma unroll
        for (int kh = 0; kh < 3; kh++)
#pragma unroll
            for (int kw = 0; kw < 3; kw++)
                in_r[ci*9 + kh*3 + kw] = in_s[ci*1089 + (ty*2+kh)*33 + (tx*2+kw)];

    int oh = OH0 + ty, ow = OW0 + tx;
    float* outp = out + (size_t)n*128*4096 + oh*64 + ow;
    for (int co = 0; co < 128; co++) {
        float acc = bias[co];
        const float* wp = &w_s[co*27];
#pragma unroll
        for (int t = 0; t < 27; t++) acc += wp[t] * in_r[t];
        outp[(size_t)co*4096] = acc;
    }
}

// ---------------- BN stats / finalize / apply ----------------
__global__ void bn_stats_kernel(const float* __restrict__ x,
                                float* __restrict__ psum, float* __restrict__ psq,
                                int C, int HW, int N, int nblk)
{
    int c = blockIdx.x, blk = blockIdx.y;
    int count = N * HW;
    float s = 0.f, sq = 0.f;
    for (int i = blk*256 + threadIdx.x; i < count; i += nblk*256) {
        int n = i / HW, hw = i - n*HW;
        float v = x[(size_t)(n*C + c)*HW + hw];
        s += v; sq += v*v;
    }
    __shared__ float rs[256], rq[256];
    rs[threadIdx.x] = s; rq[threadIdx.x] = sq;
    __syncthreads();
    for (int o = 128; o > 0; o >>= 1) {
        if (threadIdx.x < o) { rs[threadIdx.x] += rs[threadIdx.x+o]; rq[threadIdx.x] += rq[threadIdx.x+o]; }
        __syncthreads();
    }
    if (threadIdx.x == 0) { psum[c*nblk + blk] = rs[0]; psq[c*nblk + blk] = rq[0]; }
}

__global__ void bn_finalize_kernel(const float* __restrict__ psum, const float* __restrict__ psq,
                                   const float* __restrict__ g, const float* __restrict__ b,
                                   float* __restrict__ scale, float* __restrict__ shift,
                                   int nblk, float inv_count)
{
    int c = threadIdx.x;
    float s = 0.f, sq = 0.f;
    for (int i = 0; i < nblk; i++) { s += psum[c*nblk + i]; sq += psq[c*nblk + i]; }
    float mean = s * inv_count;
    float var = sq * inv_count - mean*mean;
    float r = rsqrtf(var + 1e-5f);
    float sc = g[c] * r;
    scale[c] = sc;
    shift[c] = b[c] - mean * sc;
}

__global__ void bn_relu_kernel(float* __restrict__ x,
                               const float* __restrict__ scale, const float* __restrict__ shift,
                               int HW, int C, long total)
{
    long i = (long)blockIdx.x * 256 + threadIdx.x;
    long stride = (long)gridDim.x * 256;
    for (; i < total; i += stride) {
        int c = (int)((i / HW) % C);
        float v = x[i] * scale[c] + shift[c];
        x[i] = v > 0.f ? v : 0.f;
    }
}

// ---------------- conv2: 128->256, s2, 64->32 ----------------
// grid (coB=4, tile=16, n=64); block 256.
// Each thread: 4 consecutive ow x 4 co register block, 16-ci smem chunks.
__global__ void conv2_kernel(const float* __restrict__ in,
                             const float* __restrict__ w,
                             const float* __restrict__ bias,
                             float* __restrict__ out)
{
    extern __shared__ float sm[];
    float* w_s  = sm;          // 64co * 16ci * 9 = 9216
    float* in_s = sm + 9216;   // 16 * 17 * 17 = 4624
    int n = blockIdx.z;
    int coB = blockIdx.x;
    int tile = blockIdx.y;
    int OH0 = (tile >> 2) * 8, OW0 = (tile & 3) * 8;
    int tid = threadIdx.x;
    int pxg = tid & 15;
    int cog = tid >> 4;        // 0..15, 4 co each
    int r = pxg >> 1;          // 0..7 output row
    int seg = pxg & 1;         // ow base seg*4
    int IH0 = OH0*2 - 1, IW0 = OW0*2 - 1;

    float acc[4][4];
#pragma unroll
    for (int j = 0; j < 4; j++)
#pragma unroll
        for (int p = 0; p < 4; p++) acc[j][p] = 0.f;

    for (int ci0 = 0; ci0 < 128; ci0 += 16) {
        __syncthreads();
        for (int i = tid; i < 64*16*9; i += 256) {
            int co = i / 144; int rem = i - co*144; int ci = rem / 9; int t = rem - ci*9;
            w_s[i] = w[((size_t)(coB*64 + co)*128 + ci0 + ci)*9 + t];
        }
        for (int i = tid; i < 16*289; i += 256) {
            int ci = i / 289; int rr = (i % 289) / 17; int cc = i % 17;
            int ih = IH0 + rr, iw = IW0 + cc;
            float v = 0.f;
            if (ih >= 0 && ih < 64 && iw >= 0 && iw < 64)
                v = in[((size_t)(n*128 + ci0 + ci)*64 + ih)*64 + iw];
            in_s[i] = v;
        }
        __syncthreads();

        for (int ci = 0; ci < 16; ci++) {
            float in_r[3][9];
#pragma unroll
            for (int kh = 0; kh < 3; kh++)
#pragma unroll
                for (int q = 0; q < 9; q++)
                    in_r[kh][q] = in_s[ci*289 + (r*2 + kh)*17 + seg*8 + q];
#pragma unroll
            for (int j = 0; j < 4; j++) {
                const float* wp = &w_s[((cog*4 + j)*16 + ci)*9];
#pragma unroll
                for (int kh = 0; kh < 3; kh++)
#pragma unroll
                    for (int kw = 0; kw < 3; kw++) {
                        float wv = wp[kh*3 + kw];
#pragma unroll
                        for (int p = 0; p < 4; p++)
                            acc[j][p] += wv * in_r[kh][p*2 + kw];
                    }
            }
        }
    }
    int oh = OH0 + r;
#pragma unroll
    for (int j = 0; j < 4; j++) {
        int co = coB*64 + cog*4 + j;
        float bv = bias[co];
#pragma unroll
        for (int p = 0; p < 4; p++) {
            int ow = OW0 + seg*4 + p;
            out[((size_t)(n*256 + co)*32 + oh)*32 + ow] = acc[j][p] + bv;
        }
    }
}

// ---------------- pre 1x1: 256->64 ----------------
// grid (4 s-tiles, 64 n); block 256; thread owns one spatial pos, all 64 co.
__global__ void pre_kernel(const float* __restrict__ in,
                           const float* __restrict__ w,
                           const float* __restrict__ bias,
                           float* __restrict__ out)
{
    extern __shared__ float w_s[]; // 64*256
    int n = blockIdx.y;
    int s = blockIdx.x * 256 + threadIdx.x;
    for (int i = threadIdx.x; i < 64*256; i += 256) w_s[i] = w[i];
    __syncthreads();
    float acc[64];
#pragma unroll
    for (int co = 0; co < 64; co++) acc[co] = 0.f;
    const float* ip = in + (size_t)n*256*1024 + s;
    for (int ci = 0; ci < 256; ci++) {
        float v = ip[(size_t)ci*1024];
#pragma unroll
        for (int co = 0; co < 64; co++) acc[co] += w_s[co*256 + ci] * v;
    }
    float* op = out + (size_t)n*64*1024 + s;
#pragma unroll
    for (int co = 0; co < 64; co++) op[(size_t)co*1024] = acc[co] + bias[co];
}

// ---------------- VQ ----------------
__global__ void vq_kernel(const float* __restrict__ z,
                          const float* __restrict__ cb,
                          float* __restrict__ q,
                          float* __restrict__ idx_out,
                          float* __restrict__ losspart)
{
    extern __shared__ float sm[];
    float* cb_s = sm;               // 512*64
    float* csq  = sm + NCODE*VQ_DIM; // 512
    int tid = threadIdx.x;
    for (int i = tid; i < NCODE*VQ_DIM; i += 256) cb_s[i] = cb[i];
    __syncthreads();
    for (int k = tid; k < NCODE; k += 256) {
        float s = 0.f;
#pragma unroll
        for (int d = 0; d < VQ_DIM; d++) { float c = cb_s[k*VQ_DIM + d]; s += c*c; }
        csq[k] = s;
    }
    __syncthreads();

    int sidx = blockIdx.x * 256 + tid;
    int b = sidx >> 10, hw = sidx & 1023;
    const float* zp = z + (size_t)b*64*1024 + hw;
    float zv[VQ_DIM];
    float zsq = 0.f;
#pragma unroll
    for (int d = 0; d < VQ_DIM; d++) { zv[d] = zp[(size_t)d*1024]; zsq += zv[d]*zv[d]; }

    float best = 3.4e38f; int bidx = 0;
    for (int k = 0; k < NCODE; k++) {
        const float* cp = &cb_s[k*VQ_DIM];
        float dot = 0.f;
#pragma unroll
        for (int d = 0; d < VQ_DIM; d++) dot += zv[d] * cp[d];
        float d2 = zsq - 2.f*dot + csq[k];
        if (d2 < best) { best = d2; bidx = k; }
    }

    float lsum = 0.f;
    float* qp = q + (size_t)b*64*1024 + hw;
#pragma unroll
    for (int d = 0; d < VQ_DIM; d++) {
        float c = cb_s[bidx*VQ_DIM + d];
        qp[(size_t)d*1024] = c;
        float df = zv[d] - c;
        lsum += df*df;
    }
    idx_out[sidx] = (float)bidx;

    __shared__ float red[256];
    red[tid] = lsum; __syncthreads();
    for (int o = 128; o > 0; o >>= 1) {
        if (tid < o) red[tid] += red[tid + o];
        __syncthreads();
    }
    if (tid == 0) losspart[blockIdx.x] = red[0];
}

__global__ void loss_finalize_kernel(const float* __restrict__ losspart,
                                     float* __restrict__ out_losses)
{
    __shared__ float red[256];
    red[threadIdx.x] = losspart[threadIdx.x];
    __syncthreads();
    for (int o = 128; o > 0; o >>= 1) {
        if (threadIdx.x < o) red[threadIdx.x] += red[threadIdx.x + o];
        __syncthreads();
    }
    if (threadIdx.x == 0) {
        float m = red[0] / (65536.f * 64.f);
        out_losses[0] = m;  // loss_embed
        out_losses[1] = m;  // loss_commit (identical in forward)
    }
}

// ---------------- post 1x1: 64->256 ----------------
// grid (4 s-tiles, 4 coB, 64 n)
__global__ void post_kernel(const float* __restrict__ in,
                            const float* __restrict__ w,
                            const float* __restrict__ bias,
                            float* __restrict__ out)
{
    __shared__ float w_s[64*64];
    int n = blockIdx.z, coB = blockIdx.y;
    int s = blockIdx.x * 256 + threadIdx.x;
    for (int i = threadIdx.x; i < 64*64; i += 256) {
        int co = i >> 6, ci = i & 63;
        w_s[i] = w[(size_t)(coB*64 + co)*64 + ci];
    }
    __syncthreads();
    float acc[64];
#pragma unroll
    for (int co = 0; co < 64; co++) acc[co] = 0.f;
    const float* ip = in + (size_t)n*64*1024 + s;
    for (int ci = 0; ci < 64; ci++) {
        float v = ip[(size_t)ci*1024];
#pragma unroll
        for (int co = 0; co < 64; co++) acc[co] += w_s[co*64 + ci] * v;
    }
    float* op = out + (size_t)n*256*1024 + (size_t)coB*64*1024 + s;
#pragma unroll
    for (int co = 0; co < 64; co++) op[(size_t)co*1024] = acc[co] + bias[coB*64 + co];
}

// ---------------- dec1 transpose conv: 256->128, 32->64 ----------------
// grid (coB=4, tile=16, n=64); block 256.
// Threads grouped by output parity class so tap sets are warp-uniform.
// Each thread: 4 px (class columns) x 8 co.
__global__ void dec1_kernel(const float* __restrict__ in,
                            const float* __restrict__ w,   // (256,128,3,3)
                            const float* __restrict__ bias,
                            float* __restrict__ out)
{
    extern __shared__ float sm[];
    float* w_s  = sm;          // 32ci * 32co * 9 = 9216
    float* in_s = sm + 9216;   // 32 * 9 * 9 = 2592
    int n = blockIdx.z, coB = blockIdx.x, tile = blockIdx.y;
    int OH0 = (tile >> 2) * 16, OW0 = (tile & 3) * 16;
    int IH0 = OH0 >> 1, IW0 = OW0 >> 1;
    int tid = threadIdx.x;
    int cls = tid >> 6;
    int pe_h = cls >> 1, pe_w = cls & 1;
    int cog = (tid >> 4) & 3;    // 8 co each
    int t3 = tid & 15;
    int r8 = t3 >> 1;            // class row 0..7
    int c2 = t3 & 1;             // column group: 4 class-cols each

    float acc[8][4];
#pragma unroll
    for (int j = 0; j < 8; j++)
#pragma unroll
        for (int i = 0; i < 4; i++) acc[j][i] = 0.f;

    for (int ci0 = 0; ci0 < 256; ci0 += 32) {
        __syncthreads();
        for (int i = tid; i < 32*32*9; i += 256) {
            int ci = i / 288; int rem = i - ci*288; int co = rem / 9; int t = rem - co*9;
            w_s[i] = w[((size_t)(ci0 + ci)*128 + coB*32 + co)*9 + t];
        }
        for (int i = tid; i < 32*81; i += 256) {
            int ci = i / 81; int rr = (i % 81) / 9; int cc = i % 9;
            int ih = IH0 + rr, iw = IW0 + cc;
            float v = 0.f;
            if (ih < 32 && iw < 32)
                v = in[((size_t)(n*256 + ci0 + ci)*32 + ih)*32 + iw];
            in_s[i] = v;
        }
        __syncthreads();

        for (int ci = 0; ci < 32; ci++) {
            const float* base = &in_s[ci*81];
            float row0[5], row1[5];
#pragma unroll
            for (int qq = 0; qq < 5; qq++) {
                row0[qq] = base[r8*9 + c2*4 + qq];
                row1[qq] = base[(r8+1)*9 + c2*4 + qq];
            }
            auto do_tap = [&](int kh, int kw, const float* rowv, int off) {
#pragma unroll
                for (int j = 0; j < 8; j++) {
                    float wv = w_s[(ci*32 + cog*8 + j)*9 + kh*3 + kw];
#pragma unroll
                    for (int i = 0; i < 4; i++)
                        acc[j][i] += wv * rowv[i + off];
                }
            };
            if (pe_h == 0) {
                if (pe_w == 0) { do_tap(1,1,row0,0); }
                else           { do_tap(1,0,row0,1); do_tap(1,2,row0,0); }
            } else {
                if (pe_w == 0) { do_tap(0,1,row1,0); do_tap(2,1,row0,0); }
                else           { do_tap(0,0,row1,1); do_tap(0,2,row1,0);
                                 do_tap(2,0,row0,1); do_tap(2,2,row0,0); }
            }
        }
    }
    int oh = OH0 + r8*2 + pe_h;
#pragma unroll
    for (int j = 0; j < 8; j++) {
        int co = coB*32 + cog*8 + j;
        float bv = bias[co];
#pragma unroll
        for (int i = 0; i < 4; i++) {
            int ow = OW0 + (c2*4 + i)*2 + pe_w;
            out[((size_t)(n*128 + co)*64 + oh)*64 + ow] = acc[j][i] + bv;
        }
    }
}

// ---------------- dec2 transpose conv: 128->3, 64->128, tanh ----------------
// grid (64 tiles, 64 n); block 256 (parity-classed 16x16 output tile).
__global__ void dec2_kernel(const float* __restrict__ in,
                            const float* __restrict__ w,   // (128,3,3,3)
                            const float* __restrict__ bias,
                            float* __restrict__ out)
{
    extern __shared__ float sm[];
    float* w_s  = sm;           // 128*27 = 3456
    float* in_s = sm + 3456;    // 128*81 = 10368
    int n = blockIdx.y; int tile = blockIdx.x;
    int OH0 = (tile >> 3) * 16, OW0 = (tile & 7) * 16;
    int IH0 = OH0 >> 1, IW0 = OW0 >> 1;
    int tid = threadIdx.x;
    for (int i = tid; i < 3456; i += 256) w_s[i] = w[i];
    for (int i = tid; i < 128*81; i += 256) {
        int ci = i / 81; int rr = (i % 81) / 9; int cc = i % 9;
        int ih = IH0 + rr, iw = IW0 + cc;
        float v = 0.f;
        if (ih < 64 && iw < 64)
            v = in[((size_t)(n*128 + ci)*64 + ih)*64 + iw];
        in_s[i] = v;
    }
    __syncthreads();

    int cls = tid >> 6; int pe_h = cls >> 1, pe_w = cls & 1;
    int t3 = tid & 63; int r8 = t3 >> 3, c8 = t3 & 7;
    float acc[3] = {0.f, 0.f, 0.f};

    for (int ci = 0; ci < 128; ci++) {
        const float* base = &in_s[ci*81];
        float v00 = base[r8*9 + c8];
        float v01 = base[r8*9 + c8 + 1];
        float v10 = base[(r8+1)*9 + c8];
        float v11 = base[(r8+1)*9 + c8 + 1];
        const float* wp = &w_s[ci*27];
        if (pe_h == 0) {
            if (pe_w == 0) {
#pragma unroll
                for (int co = 0; co < 3; co++) acc[co] += wp[co*9 + 4] * v00;          // kh=1,kw=1
            } else {
#pragma unroll
                for (int co = 0; co < 3; co++) acc[co] += wp[co*9 + 3] * v01 + wp[co*9 + 5] * v00; // kh=1,kw=0/2
            }
        } else {
            if (pe_w == 0) {
#pragma unroll
                for (int co = 0; co < 3; co++) acc[co] += wp[co*9 + 1] * v10 + wp[co*9 + 7] * v00; // kh=0/2,kw=1
            } else {
#pragma unroll
                for (int co = 0; co < 3; co++)
                    acc[co] += wp[co*9 + 0] * v11 + wp[co*9 + 2] * v10
                             + wp[co*9 + 6] * v01 + wp[co*9 + 8] * v00;
            }
        }
    }
    int oh = OH0 + r8*2 + pe_h, ow = OW0 + c8*2 + pe_w;
#pragma unroll
    for (int co = 0; co < 3; co++)
        out[((size_t)(n*3 + co)*128 + oh)*128 + ow] = tanhf(acc[co] + bias[co]);
}

// ---------------- host launch ----------------
static float* sym_addr(const void* sym)
{
    void* p = nullptr;
    cudaGetSymbolAddress(&p, sym);
    return (float*)p;
}

extern "C" void kernel_launch(void* const* d_in, const int* in_sizes, int n_in,
                              void* d_out, int out_size)
{
    const float* x       = (const float*)d_in[0];
    const float* enc1_w  = (const float*)d_in[1];
    const float* enc1_b  = (const float*)d_in[2];
    const float* bn1_g   = (const float*)d_in[3];
    const float* bn1_b   = (const float*)d_in[4];
    const float* enc2_w  = (const float*)d_in[5];
    const float* enc2_b  = (const float*)d_in[6];
    const float* pre_w   = (const float*)d_in[7];
    const float* pre_b   = (const float*)d_in[8];
    const float* codebook= (const float*)d_in[9];
    const float* post_w  = (const float*)d_in[10];
    const float* post_b  = (const float*)d_in[11];
    const float* dec1_w  = (const float*)d_in[12];
    const float* dec1_b  = (const float*)d_in[13];
    const float* dbn1_g  = (const float*)d_in[14];
    const float* dbn1_b  = (const float*)d_in[15];
    const float* dec2_w  = (const float*)d_in[16];
    const float* dec2_b  = (const float*)d_in[17];

    float* out = (float*)d_out;
    float* out_losses = out + RECON_ELEMS;
    float* out_idx    = out + RECON_ELEMS + 2;

    float* h1 = sym_addr(g_h1);
    float* h2 = sym_addr(g_h2);
    float* z  = sym_addr(g_z);
    float* q  = sym_addr(g_q);
    float* d  = sym_addr(g_d);
    float* d1 = sym_addr(g_d1);
    float* psum = sym_addr(g_psum);
    float* psq  = sym_addr(g_psq);
    float* sc   = sym_addr(g_scale);
    float* sh   = sym_addr(g_shift);
    float* lp   = sym_addr(g_losspart);

    cudaFuncSetAttribute(conv2_kernel, cudaFuncAttributeMaxDynamicSharedMemorySize, 55360);
    cudaFuncSetAttribute(pre_kernel,   cudaFuncAttributeMaxDynamicSharedMemorySize, 65536);
    cudaFuncSetAttribute(vq_kernel,    cudaFuncAttributeMaxDynamicSharedMemorySize, 133120);
    cudaFuncSetAttribute(dec1_kernel,  cudaFuncAttributeMaxDynamicSharedMemorySize, 47232);
    cudaFuncSetAttribute(dec2_kernel,  cudaFuncAttributeMaxDynamicSharedMemorySize, 55296);

    const float inv_cnt = 1.f / 262144.f;  // N*H*W for both BN layers

    // encoder
    conv1_kernel<<<dim3(4,4,64), 256>>>(x, enc1_w, enc1_b, h1);
    bn_stats_kernel<<<dim3(128,64), 256>>>(h1, psum, psq, 128, 4096, 64, 64);
    bn_finalize_kernel<<<1,128>>>(psum, psq, bn1_g, bn1_b, sc, sh, 64, inv_cnt);
    bn_relu_kernel<<<8192,256>>>(h1, sc, sh, 4096, 128, (long)H1_ELEMS);
    conv2_kernel<<<dim3(4,16,64), 256, 55360>>>(h1, enc2_w, enc2_b, h2);
    pre_kernel<<<dim3(4,64), 256, 65536>>>(h2, pre_w, pre_b, z);

    // VQ
    vq_kernel<<<256, 256, 133120>>>(z, codebook, q, out_idx, lp);
    loss_finalize_kernel<<<1,256>>>(lp, out_losses);

    // decoder
    post_kernel<<<dim3(4,4,64), 256>>>(q, post_w, post_b, d);
    dec1_kernel<<<dim3(4,16,64), 256, 47232>>>(d, dec1_w, dec1_b, d1);
    bn_stats_kernel<<<dim3(128,64), 256>>>(d1, psum, psq, 128, 4096, 64, 64);
    bn_finalize_kernel<<<1,128>>>(psum, psq, dbn1_g, dbn1_b, sc, sh, 64, inv_cnt);
    bn_relu_kernel<<<8192,256>>>(d1, sc, sh, 4096, 128, (long)D1_ELEMS);
    dec2_kernel<<<dim3(64,64), 256, 55296>>>(d1, dec2_w, dec2_b, out);

    (void)in_sizes; (void)n_in; (void)out_size;
}

// round 3
// speedup vs baseline: 1.0621x; 1.0621x over previous
#include <cuda_runtime.h>
#include <cstdint>

// ---------------- problem constants ----------------
// conv1: 3 -> 128, 128x128 -> 64x64, k3 s2 p1
// conv2: 128 -> 256, 64x64 -> 32x32, k3 s2 p1  (input = relu(bn(conv1)), fused)
// pre:   256 -> 64 (1x1)
// VQ:    512 codes x 64 dims
// post:  64 -> 256 (1x1)
// dec1:  convT 256 -> 128, 32x32 -> 64x64, k3 s2 p1 op1
// dec2:  convT 128 -> 3,  64x64 -> 128x128, k3 s2 p1 op1 (input = relu(bn(dec1)), fused)

#define H1_ELEMS (64*128*64*64)
#define H2_ELEMS (64*256*32*32)
#define Z_ELEMS  (64*64*32*32)
#define D_ELEMS  (64*256*32*32)
#define D1_ELEMS (64*128*64*64)

#define RECON_ELEMS (64*3*128*128)
#define VQ_DIM 64
#define NCODE 512

__device__ float g_h1[H1_ELEMS];
__device__ float g_h2[H2_ELEMS];
__device__ float g_z[Z_ELEMS];
__device__ float g_q[Z_ELEMS];
__device__ float g_d[D_ELEMS];
__device__ float g_d1[D1_ELEMS];
__device__ float g_psum[128*64];
__device__ float g_psq[128*64];
__device__ float g_scale[128];
__device__ float g_shift[128];
__device__ float g_losspart[256];

// ---------------- conv1: 3->128, s2, 128->64 ----------------
// grid (4,4,64); block 256 = one thread per output px; weights float4 from smem.
__global__ void conv1_kernel(const float* __restrict__ x,
                             const float* __restrict__ w,
                             const float* __restrict__ bias,
                             float* __restrict__ out)
{
    __shared__ float w_s[128*28];     // padded stride 28 (16B aligned rows)
    __shared__ float in_s[3*33*33];
    int n = blockIdx.z;
    int OH0 = blockIdx.y * 16, OW0 = blockIdx.x * 16;
    int tid = threadIdx.x;

    for (int i = tid; i < 128*27; i += 256) {
        int co = i / 27, t = i - co*27;
        w_s[co*28 + t] = w[i];
    }
    for (int co = tid; co < 128; co += 256) w_s[co*28 + 27] = 0.f;

    int IH0 = OH0*2 - 1, IW0 = OW0*2 - 1;
    for (int i = tid; i < 3*33*33; i += 256) {
        int ci = i / 1089; int r = (i % 1089) / 33; int c = i % 33;
        int ih = IH0 + r, iw = IW0 + c;
        float v = 0.f;
        if (ih >= 0 && ih < 128 && iw >= 0 && iw < 128)
            v = x[((n*3 + ci)*128 + ih)*128 + iw];
        in_s[i] = v;
    }
    __syncthreads();

    int ty = tid >> 4, tx = tid & 15;
    float in_r[28];
#pragma unroll
    for (int ci = 0; ci < 3; ci++)
#pragma unroll
        for (int kh = 0; kh < 3; kh++)
#pragma unroll
            for (int kw = 0; kw < 3; kw++)
                in_r[ci*9 + kh*3 + kw] = in_s[ci*1089 + (ty*2+kh)*33 + (tx*2+kw)];
    in_r[27] = 0.f;

    int oh = OH0 + ty, ow = OW0 + tx;
    float* outp = out + (size_t)n*128*4096 + oh*64 + ow;
    const float4* w4p = reinterpret_cast<const float4*>(w_s);
    for (int co = 0; co < 128; co++) {
        float acc = bias[co];
#pragma unroll
        for (int u = 0; u < 7; u++) {
            float4 w4 = w4p[co*7 + u];
            acc += w4.x * in_r[u*4+0];
            acc += w4.y * in_r[u*4+1];
            acc += w4.z * in_r[u*4+2];
            acc += w4.w * in_r[u*4+3];
        }
        outp[(size_t)co*4096] = acc;
    }
}

// ---------------- BN stats (float4) / finalize ----------------
// x laid out (N, C, 4096). One channel per blockIdx.x, nblk partial blocks.
__global__ void bn_stats_kernel(const float* __restrict__ x,
                                float* __restrict__ psum, float* __restrict__ psq,
                                int C, int nblk)
{
    int c = blockIdx.x, blk = blockIdx.y;
    float s = 0.f, sq = 0.f;
    // per channel: 64 planes of 1024 float4
    int total4 = 64 * 1024;
    for (int i = blk*256 + threadIdx.x; i < total4; i += nblk*256) {
        int n = i >> 10, off = i & 1023;
        const float4* p = reinterpret_cast<const float4*>(x + ((size_t)(n*C + c))*4096);
        float4 v = p[off];
        s  += v.x + v.y + v.z + v.w;
        sq += v.x*v.x + v.y*v.y + v.z*v.z + v.w*v.w;
    }
    __shared__ float rs[256], rq[256];
    rs[threadIdx.x] = s; rq[threadIdx.x] = sq;
    __syncthreads();
    for (int o = 128; o > 0; o >>= 1) {
        if (threadIdx.x < o) { rs[threadIdx.x] += rs[threadIdx.x+o]; rq[threadIdx.x] += rq[threadIdx.x+o]; }
        __syncthreads();
    }
    if (threadIdx.x == 0) { psum[c*nblk + blk] = rs[0]; psq[c*nblk + blk] = rq[0]; }
}

__global__ void bn_finalize_kernel(const float* __restrict__ psum, const float* __restrict__ psq,
                                   const float* __restrict__ g, const float* __restrict__ b,
                                   float* __restrict__ scale, float* __restrict__ shift,
                                   int nblk, float inv_count)
{
    int c = threadIdx.x;
    float s = 0.f, sq = 0.f;
    for (int i = 0; i < nblk; i++) { s += psum[c*nblk + i]; sq += psq[c*nblk + i]; }
    float mean = s * inv_count;
    float var = sq * inv_count - mean*mean;
    float r = rsqrtf(var + 1e-5f);
    float sc = g[c] * r;
    scale[c] = sc;
    shift[c] = b[c] - mean * sc;
}

// ---------------- conv2: 128->256, s2, 64->32, fused BN+ReLU on input ----------------
// grid (coB=4, tile=16, n=64); block 256; thread: 4 ow x 4 co.
__global__ void conv2_kernel(const float* __restrict__ in,
                             const float* __restrict__ w,
                             const float* __restrict__ bias,
                             const float* __restrict__ scale,
                             const float* __restrict__ shift,
                             float* __restrict__ out)
{
    extern __shared__ float sm[];
    float* w_s  = sm;            // [ci16][t9][co64] = 9216
    float* in_s = sm + 9216;     // 16 * 17 * 17 = 4624
    float* sc_s = sm + 9216 + 4624;       // 128
    float* sh_s = sc_s + 128;             // 128
    int n = blockIdx.z;
    int coB = blockIdx.x;
    int tile = blockIdx.y;
    int OH0 = (tile >> 2) * 8, OW0 = (tile & 3) * 8;
    int tid = threadIdx.x;
    int pxg = tid & 15;
    int cog = tid >> 4;        // 0..15, 4 co each
    int r = pxg >> 1;
    int seg = pxg & 1;
    int IH0 = OH0*2 - 1, IW0 = OW0*2 - 1;

    for (int i = tid; i < 128; i += 256) { sc_s[i] = scale[i]; sh_s[i] = shift[i]; }

    float acc[4][4];
#pragma unroll
    for (int j = 0; j < 4; j++)
#pragma unroll
        for (int p = 0; p < 4; p++) acc[j][p] = 0.f;

    for (int ci0 = 0; ci0 < 128; ci0 += 16) {
        __syncthreads();
        // weights transposed: w_s[(ci*9 + t)*64 + co]
        for (int i = tid; i < 16*9*64; i += 256) {
            int ci = i / 576; int rem = i - ci*576; int t = rem >> 6; int co = rem & 63;
            w_s[i] = w[((size_t)(coB*64 + co)*128 + ci0 + ci)*9 + t];
        }
        for (int i = tid; i < 16*289; i += 256) {
            int ci = i / 289; int rr = (i % 289) / 17; int cc = i % 17;
            int ih = IH0 + rr, iw = IW0 + cc;
            float v = 0.f;
            if (ih >= 0 && ih < 64 && iw >= 0 && iw < 64) {
                float raw = in[((size_t)(n*128 + ci0 + ci)*64 + ih)*64 + iw];
                v = fmaxf(fmaf(raw, sc_s[ci0 + ci], sh_s[ci0 + ci]), 0.f);
            }
            in_s[i] = v;
        }
        __syncthreads();

        for (int ci = 0; ci < 16; ci++) {
            float in_r[3][9];
#pragma unroll
            for (int kh = 0; kh < 3; kh++)
#pragma unroll
                for (int q = 0; q < 9; q++)
                    in_r[kh][q] = in_s[ci*289 + (r*2 + kh)*17 + seg*8 + q];
#pragma unroll
            for (int kh = 0; kh < 3; kh++)
#pragma unroll
                for (int kw = 0; kw < 3; kw++) {
                    int t = kh*3 + kw;
                    float4 w4 = *reinterpret_cast<const float4*>(&w_s[(ci*9 + t)*64 + cog*4]);
                    float wv[4] = {w4.x, w4.y, w4.z, w4.w};
#pragma unroll
                    for (int j = 0; j < 4; j++)
#pragma unroll
                        for (int p = 0; p < 4; p++)
                            acc[j][p] += wv[j] * in_r[kh][p*2 + kw];
                }
        }
    }
    int oh = OH0 + r;
#pragma unroll
    for (int j = 0; j < 4; j++) {
        int co = coB*64 + cog*4 + j;
        float bv = bias[co];
#pragma unroll
        for (int p = 0; p < 4; p++) {
            int ow = OW0 + seg*4 + p;
            out[((size_t)(n*256 + co)*32 + oh)*32 + ow] = acc[j][p] + bv;
        }
    }
}

// ---------------- pre 1x1: 256->64 ----------------
// grid (4 s-tiles, 2 co-halves, 64 n); block 256; thread: 1 px, 32 co.
__global__ void pre_kernel(const float* __restrict__ in,
                           const float* __restrict__ w,
                           const float* __restrict__ bias,
                           float* __restrict__ out)
{
    __shared__ float w_t[256*32];   // [ci][co]
    int n = blockIdx.z, coH = blockIdx.y;
    int s = blockIdx.x * 256 + threadIdx.x;
    for (int i = threadIdx.x; i < 256*32; i += 256) {
        int ci = i >> 5, co = i & 31;
        w_t[i] = w[(size_t)(coH*32 + co)*256 + ci];
    }
    __syncthreads();
    float acc[32];
#pragma unroll
    for (int co = 0; co < 32; co++) acc[co] = 0.f;
    const float* ip = in + (size_t)n*256*1024 + s;
    const float4* w4p = reinterpret_cast<const float4*>(w_t);
    for (int ci = 0; ci < 256; ci++) {
        float v = ip[(size_t)ci*1024];
#pragma unroll
        for (int k = 0; k < 8; k++) {
            float4 w4 = w4p[ci*8 + k];
            acc[k*4+0] += w4.x * v;
            acc[k*4+1] += w4.y * v;
            acc[k*4+2] += w4.z * v;
            acc[k*4+3] += w4.w * v;
        }
    }
    float* op = out + (size_t)n*64*1024 + (size_t)coH*32*1024 + s;
#pragma unroll
    for (int co = 0; co < 32; co++) op[(size_t)co*1024] = acc[co] + bias[coH*32 + co];
}

// ---------------- VQ (float4 codebook) ----------------
__global__ void vq_kernel(const float* __restrict__ z,
                          const float* __restrict__ cb,
                          float* __restrict__ q,
                          float* __restrict__ idx_out,
                          float* __restrict__ losspart)
{
    extern __shared__ float sm[];
    float* cb_s = sm;                 // 512*64
    float* csq  = sm + NCODE*VQ_DIM;  // 512
    int tid = threadIdx.x;
    for (int i = tid; i < NCODE*VQ_DIM; i += 256) cb_s[i] = cb[i];
    __syncthreads();
    for (int k = tid; k < NCODE; k += 256) {
        float s = 0.f;
#pragma unroll
        for (int d = 0; d < VQ_DIM; d++) { float c = cb_s[k*VQ_DIM + d]; s += c*c; }
        csq[k] = s;
    }
    __syncthreads();

    int sidx = blockIdx.x * 256 + tid;
    int b = sidx >> 10, hw = sidx & 1023;
    const float* zp = z + (size_t)b*64*1024 + hw;
    float zv[VQ_DIM];
    float zsq = 0.f;
#pragma unroll
    for (int d = 0; d < VQ_DIM; d++) { zv[d] = zp[(size_t)d*1024]; zsq += zv[d]*zv[d]; }

    const float4* cb4 = reinterpret_cast<const float4*>(cb_s);
    float best = 3.4e38f; int bidx = 0;
    for (int k = 0; k < NCODE; k++) {
        float dot = 0.f;
#pragma unroll
        for (int u = 0; u < 16; u++) {
            float4 c4 = cb4[k*16 + u];
            dot += zv[u*4+0] * c4.x;
            dot += zv[u*4+1] * c4.y;
            dot += zv[u*4+2] * c4.z;
            dot += zv[u*4+3] * c4.w;
        }
        float d2 = zsq - 2.f*dot + csq[k];
        if (d2 < best) { best = d2; bidx = k; }
    }

    float lsum = 0.f;
    float* qp = q + (size_t)b*64*1024 + hw;
#pragma unroll
    for (int d = 0; d < VQ_DIM; d++) {
        float c = cb_s[bidx*VQ_DIM + d];
        qp[(size_t)d*1024] = c;
        float df = zv[d] - c;
        lsum += df*df;
    }
    idx_out[sidx] = (float)bidx;

    __shared__ float red[256];
    red[tid] = lsum; __syncthreads();
    for (int o = 128; o > 0; o >>= 1) {
        if (tid < o) red[tid] += red[tid + o];
        __syncthreads();
    }
    if (tid == 0) losspart[blockIdx.x] = red[0];
}

__global__ void loss_finalize_kernel(const float* __restrict__ losspart,
                                     float* __restrict__ out_losses)
{
    __shared__ float red[256];
    red[threadIdx.x] = losspart[threadIdx.x];
    __syncthreads();
    for (int o = 128; o > 0; o >>= 1) {
        if (threadIdx.x < o) red[threadIdx.x] += red[threadIdx.x + o];
        __syncthreads();
    }
    if (threadIdx.x == 0) {
        float m = red[0] / (65536.f * 64.f);
        out_losses[0] = m;
        out_losses[1] = m;
    }
}

// ---------------- post 1x1: 64->256 ----------------
// grid (4 s-tiles, 4 coB, 64 n); block 256; thread: 1 px, 64 co.
__global__ void post_kernel(const float* __restrict__ in,
                            const float* __restrict__ w,
                            const float* __restrict__ bias,
                            float* __restrict__ out)
{
    __shared__ float w_t[64*64];    // [ci][co]
    int n = blockIdx.z, coB = blockIdx.y;
    int s = blockIdx.x * 256 + threadIdx.x;
    for (int i = threadIdx.x; i < 64*64; i += 256) {
        int ci = i >> 6, co = i & 63;
        w_t[i] = w[(size_t)(coB*64 + co)*64 + ci];
    }
    __syncthreads();
    float acc[64];
#pragma unroll
    for (int co = 0; co < 64; co++) acc[co] = 0.f;
    const float* ip = in + (size_t)n*64*1024 + s;
    const float4* w4p = reinterpret_cast<const float4*>(w_t);
    for (int ci = 0; ci < 64; ci++) {
        float v = ip[(size_t)ci*1024];
#pragma unroll
        for (int k = 0; k < 16; k++) {
            float4 w4 = w4p[ci*16 + k];
            acc[k*4+0] += w4.x * v;
            acc[k*4+1] += w4.y * v;
            acc[k*4+2] += w4.z * v;
            acc[k*4+3] += w4.w * v;
        }
    }
    float* op = out + (size_t)n*256*1024 + (size_t)coB*64*1024 + s;
#pragma unroll
    for (int co = 0; co < 64; co++) op[(size_t)co*1024] = acc[co] + bias[coB*64 + co];
}

// ---------------- dec1 transpose conv: 256->128, 32->64 ----------------
// grid (coB=4, tile=16, n=64); block 256; parity-classed; thread: 4 px x 8 co.
__global__ void dec1_kernel(const float* __restrict__ in,
                            const float* __restrict__ w,   // (256,128,3,3)
                            const float* __restrict__ bias,
                            float* __restrict__ out)
{
    extern __shared__ float sm[];
    float* w_s  = sm;          // [ci32][t9][co32] = 9216
    float* in_s = sm + 9216;   // 32 * 9 * 9 = 2592
    int n = blockIdx.z, coB = blockIdx.x, tile = blockIdx.y;
    int OH0 = (tile >> 2) * 16, OW0 = (tile & 3) * 16;
    int IH0 = OH0 >> 1, IW0 = OW0 >> 1;
    int tid = threadIdx.x;
    int cls = tid >> 6;
    int pe_h = cls >> 1, pe_w = cls & 1;
    int cog = (tid >> 4) & 3;    // 8 co each
    int t3 = tid & 15;
    int r8 = t3 >> 1;
    int c2 = t3 & 1;

    float acc[8][4];
#pragma unroll
    for (int j = 0; j < 8; j++)
#pragma unroll
        for (int i = 0; i < 4; i++) acc[j][i] = 0.f;

    for (int ci0 = 0; ci0 < 256; ci0 += 32) {
        __syncthreads();
        // weights transposed: w_s[(ci*9 + t)*32 + co]
        for (int i = tid; i < 32*9*32; i += 256) {
            int ci = i / 288; int rem = i - ci*288; int t = rem >> 5; int co = rem & 31;
            w_s[i] = w[((size_t)(ci0 + ci)*128 + coB*32 + co)*9 + t];
        }
        for (int i = tid; i < 32*81; i += 256) {
            int ci = i / 81; int rr = (i % 81) / 9; int cc = i % 9;
            int ih = IH0 + rr, iw = IW0 + cc;
            float v = 0.f;
            if (ih < 32 && iw < 32)
                v = in[((size_t)(n*256 + ci0 + ci)*32 + ih)*32 + iw];
            in_s[i] = v;
        }
        __syncthreads();

        for (int ci = 0; ci < 32; ci++) {
            const float* base = &in_s[ci*81];
            float row0[5], row1[5];
#pragma unroll
            for (int qq = 0; qq < 5; qq++) {
                row0[qq] = base[r8*9 + c2*4 + qq];
                row1[qq] = base[(r8+1)*9 + c2*4 + qq];
            }
            auto do_tap = [&](int kh, int kw, const float* rowv, int off) {
                int t = kh*3 + kw;
                const float4* wp4 = reinterpret_cast<const float4*>(&w_s[(ci*9 + t)*32 + cog*8]);
                float4 wa = wp4[0], wb = wp4[1];
                float wv[8] = {wa.x, wa.y, wa.z, wa.w, wb.x, wb.y, wb.z, wb.w};
#pragma unroll
                for (int j = 0; j < 8; j++)
#pragma unroll
                    for (int i = 0; i < 4; i++)
                        acc[j][i] += wv[j] * rowv[i + off];
            };
            if (pe_h == 0) {
                if (pe_w == 0) { do_tap(1,1,row0,0); }
                else           { do_tap(1,0,row0,1); do_tap(1,2,row0,0); }
            } else {
                if (pe_w == 0) { do_tap(0,1,row1,0); do_tap(2,1,row0,0); }
                else           { do_tap(0,0,row1,1); do_tap(0,2,row1,0);
                                 do_tap(2,0,row0,1); do_tap(2,2,row0,0); }
            }
        }
    }
    int oh = OH0 + r8*2 + pe_h;
#pragma unroll
    for (int j = 0; j < 8; j++) {
        int co = coB*32 + cog*8 + j;
        float bv = bias[co];
#pragma unroll
        for (int i = 0; i < 4; i++) {
            int ow = OW0 + (c2*4 + i)*2 + pe_w;
            out[((size_t)(n*128 + co)*64 + oh)*64 + ow] = acc[j][i] + bv;
        }
    }
}

// ---------------- dec2 transpose conv: 128->3, 64->128, fused BN+ReLU in, tanh out ----------------
// grid (64 tiles, 64 n); block 256.
__global__ void dec2_kernel(const float* __restrict__ in,
                            const float* __restrict__ w,   // (128,3,3,3)
                            const float* __restrict__ bias,
                            const float* __restrict__ scale,
                            const float* __restrict__ shift,
                            float* __restrict__ out)
{
    extern __shared__ float sm[];
    float* w_s  = sm;           // 128*27 = 3456
    float* in_s = sm + 3456;    // 128*81 = 10368
    float* sc_s = sm + 3456 + 10368;  // 128
    float* sh_s = sc_s + 128;         // 128
    int n = blockIdx.y; int tile = blockIdx.x;
    int OH0 = (tile >> 3) * 16, OW0 = (tile & 7) * 16;
    int IH0 = OH0 >> 1, IW0 = OW0 >> 1;
    int tid = threadIdx.x;
    for (int i = tid; i < 3456; i += 256) w_s[i] = w[i];
    for (int i = tid; i < 128; i += 256) { sc_s[i] = scale[i]; sh_s[i] = shift[i]; }
    __syncthreads();
    for (int i = tid; i < 128*81; i += 256) {
        int ci = i / 81; int rr = (i % 81) / 9; int cc = i % 9;
        int ih = IH0 + rr, iw = IW0 + cc;
        float v = 0.f;
        if (ih < 64 && iw < 64) {
            float raw = in[((size_t)(n*128 + ci)*64 + ih)*64 + iw];
            v = fmaxf(fmaf(raw, sc_s[ci], sh_s[ci]), 0.f);
        }
        in_s[i] = v;
    }
    __syncthreads();

    int cls = tid >> 6; int pe_h = cls >> 1, pe_w = cls & 1;
    int t3 = tid & 63; int r8 = t3 >> 3, c8 = t3 & 7;
    float acc[3] = {0.f, 0.f, 0.f};

    for (int ci = 0; ci < 128; ci++) {
        const float* base = &in_s[ci*81];
        float v00 = base[r8*9 + c8];
        float v01 = base[r8*9 + c8 + 1];
        float v10 = base[(r8+1)*9 + c8];
        float v11 = base[(r8+1)*9 + c8 + 1];
        const float* wp = &w_s[ci*27];
        if (pe_h == 0) {
            if (pe_w == 0) {
#pragma unroll
                for (int co = 0; co < 3; co++) acc[co] += wp[co*9 + 4] * v00;
            } else {
#pragma unroll
                for (int co = 0; co < 3; co++) acc[co] += wp[co*9 + 3] * v01 + wp[co*9 + 5] * v00;
            }
        } else {
            if (pe_w == 0) {
#pragma unroll
                for (int co = 0; co < 3; co++) acc[co] += wp[co*9 + 1] * v10 + wp[co*9 + 7] * v00;
            } else {
#pragma unroll
                for (int co = 0; co < 3; co++)
                    acc[co] += wp[co*9 + 0] * v11 + wp[co*9 + 2] * v10
                             + wp[co*9 + 6] * v01 + wp[co*9 + 8] * v00;
            }
        }
    }
    int oh = OH0 + r8*2 + pe_h, ow = OW0 + c8*2 + pe_w;
#pragma unroll
    for (int co = 0; co < 3; co++)
        out[((size_t)(n*3 + co)*128 + oh)*128 + ow] = tanhf(acc[co] + bias[co]);
}

// ---------------- host launch ----------------
static float* sym_addr(const void* sym)
{
    void* p = nullptr;
    cudaGetSymbolAddress(&p, sym);
    return (float*)p;
}

extern "C" void kernel_launch(void* const* d_in, const int* in_sizes, int n_in,
                              void* d_out, int out_size)
{
    const float* x       = (const float*)d_in[0];
    const float* enc1_w  = (const float*)d_in[1];
    const float* enc1_b  = (const float*)d_in[2];
    const float* bn1_g   = (const float*)d_in[3];
    const float* bn1_b   = (const float*)d_in[4];
    const float* enc2_w  = (const float*)d_in[5];
    const float* enc2_b  = (const float*)d_in[6];
    const float* pre_w   = (const float*)d_in[7];
    const float* pre_b   = (const float*)d_in[8];
    const float* codebook= (const float*)d_in[9];
    const float* post_w  = (const float*)d_in[10];
    const float* post_b  = (const float*)d_in[11];
    const float* dec1_w  = (const float*)d_in[12];
    const float* dec1_b  = (const float*)d_in[13];
    const float* dbn1_g  = (const float*)d_in[14];
    const float* dbn1_b  = (const float*)d_in[15];
    const float* dec2_w  = (const float*)d_in[16];
    const float* dec2_b  = (const float*)d_in[17];

    float* out = (float*)d_out;
    float* out_losses = out + RECON_ELEMS;
    float* out_idx    = out + RECON_ELEMS + 2;

    float* h1 = sym_addr(g_h1);
    float* h2 = sym_addr(g_h2);
    float* z  = sym_addr(g_z);
    float* q  = sym_addr(g_q);
    float* d  = sym_addr(g_d);
    float* d1 = sym_addr(g_d1);
    float* psum = sym_addr(g_psum);
    float* psq  = sym_addr(g_psq);
    float* sc   = sym_addr(g_scale);
    float* sh   = sym_addr(g_shift);
    float* lp   = sym_addr(g_losspart);

    cudaFuncSetAttribute(conv2_kernel, cudaFuncAttributeMaxDynamicSharedMemorySize, 57344);
    cudaFuncSetAttribute(vq_kernel,    cudaFuncAttributeMaxDynamicSharedMemorySize, 133120);
    cudaFuncSetAttribute(dec1_kernel,  cudaFuncAttributeMaxDynamicSharedMemorySize, 47232);
    cudaFuncSetAttribute(dec2_kernel,  cudaFuncAttributeMaxDynamicSharedMemorySize, 57344);

    const float inv_cnt = 1.f / 262144.f;  // N*H*W for both BN layers
    const int NBLK = 32;

    // encoder
    conv1_kernel<<<dim3(4,4,64), 256>>>(x, enc1_w, enc1_b, h1);
    bn_stats_kernel<<<dim3(128,NBLK), 256>>>(h1, psum, psq, 128, NBLK);
    bn_finalize_kernel<<<1,128>>>(psum, psq, bn1_g, bn1_b, sc, sh, NBLK, inv_cnt);
    conv2_kernel<<<dim3(4,16,64), 256, 57344>>>(h1, enc2_w, enc2_b, sc, sh, h2);
    pre_kernel<<<dim3(4,2,64), 256>>>(h2, pre_w, pre_b, z);

    // VQ
    vq_kernel<<<256, 256, 133120>>>(z, codebook, q, out_idx, lp);
    loss_finalize_kernel<<<1,256>>>(lp, out_losses);

    // decoder
    post_kernel<<<dim3(4,4,64), 256>>>(q, post_w, post_b, d);
    dec1_kernel<<<dim3(4,16,64), 256, 47232>>>(d, dec1_w, dec1_b, d1);
    bn_stats_kernel<<<dim3(128,NBLK), 256>>>(d1, psum, psq, 128, NBLK);
    bn_finalize_kernel<<<1,128>>>(psum, psq, dbn1_g, dbn1_b, sc, sh, NBLK, inv_cnt);
    dec2_kernel<<<dim3(64,64), 256, 57344>>>(d1, dec2_w, dec2_b, sc, sh, out);

    (void)in_sizes; (void)n_in; (void)out_size;
}